// round 7
// baseline (speedup 1.0000x reference)
#include <cuda_runtime.h>
#include <cstdint>

// Fixed shapes: logits [2, 2048, 32000] fp32, labels [2, 2048] (int32 on device)
#define VOCAB   32000
#define SEQ     2048
#define HVEC    4000               // float4 per half-row (16000 floats)
#define THREADS 160                // 4000 / 160 = 25 exact iterations
#define ITERS   (HVEC / THREADS)   // 25
#define NW      (THREADS / 32)     // 5 warps
#define POS_INF __int_as_float(0x7f800000)
#define INVALID_CNT 0x7fffffff

// Per-half partials (slot = 2*row + half), per-row tickets, per-row counts.
__device__ float        g_ps1[8192];
__device__ float        g_ps2[8192];
__device__ int          g_pcnt[8192];
__device__ int          g_tick[8192];      // zero-init; self-resetting
__device__ int          g_cnt[8192];
__device__ unsigned int g_ticket = 0;      // finalize ticket; self-resetting

__global__ void __launch_bounds__(THREADS, 12)
fused_kernel(const float* __restrict__ logits,
             const int* __restrict__ labels,
             float* __restrict__ out, int N) {
    const int row  = blockIdx.x >> 1;
    const int half = blockIdx.x & 1;
    const int s    = row % SEQ;
    const int b    = row / SEQ;
    const int tid  = threadIdx.x;

    // shift labels left by one; last position of each sequence is ignored
    int lab = (s < SEQ - 1) ? labels[b * SEQ + s + 1] : -100;
    const bool valid = (lab >= 0) && (lab < VOCAB);

    const float* __restrict__ lg = logits + (long long)row * VOCAB;
    const float xl = valid ? __ldg(lg + lab) : POS_INF;

    // Direct (unshifted) accumulation: safe for |logit| << 88.
    float s1a = 0.0f, s1b = 0.0f;
    float s2a = 0.0f, s2b = 0.0f;
    int cnt = 0;

    const float4* __restrict__ lg4 =
        reinterpret_cast<const float4*>(lg) + half * HVEC;
    #pragma unroll 5
    for (int it = 0; it < ITERS; ++it) {
        float4 v = __ldcs(&lg4[tid + it * THREADS]);   // streaming, evict-first
        float ex = __expf(v.x);
        float ey = __expf(v.y);
        float ez = __expf(v.z);
        float ew = __expf(v.w);
        cnt += (v.x > xl) ? 1 : 0;
        cnt += (v.y > xl) ? 1 : 0;
        cnt += (v.z > xl) ? 1 : 0;
        cnt += (v.w > xl) ? 1 : 0;
        s1a += ex;                s1b += ey;
        s2a = fmaf(ex, v.x, s2a); s2b = fmaf(ey, v.y, s2b);
        s1a += ez;                s1b += ew;
        s2a = fmaf(ez, v.z, s2a); s2b = fmaf(ew, v.w, s2b);
    }
    float s1 = s1a + s1b;
    float s2 = s2a + s2b;

    // warp reduction
    #pragma unroll
    for (int off = 16; off > 0; off >>= 1) {
        s1  += __shfl_down_sync(0xffffffffu, s1, off);
        s2  += __shfl_down_sync(0xffffffffu, s2, off);
        cnt += __shfl_down_sync(0xffffffffu, cnt, off);
    }

    // cross-warp reduction (NW = 5 warps)
    __shared__ float ss1[NW], ss2[NW];
    __shared__ int   sc[NW];
    __shared__ int   s_last;
    const int wid = tid >> 5;
    const int lid = tid & 31;
    if (lid == 0) { ss1[wid] = s1; ss2[wid] = s2; sc[wid] = cnt; }
    __syncthreads();

    if (tid == 0) {
        s1 = ss1[0]; s2 = ss2[0]; cnt = sc[0];
        #pragma unroll
        for (int w = 1; w < NW; w++) { s1 += ss1[w]; s2 += ss2[w]; cnt += sc[w]; }

        // publish this half's partials, then take the per-row ticket
        const int slot = 2 * row + half;
        g_ps1[slot]  = s1;
        g_ps2[slot]  = s2;
        g_pcnt[slot] = cnt;
        __threadfence();
        int t = atomicAdd(&g_tick[row], 1);
        int last_half = (t == 1);

        if (last_half) {
            __threadfence();
            const int other = 2 * row + (1 - half);
            s1  += g_ps1[other];      // 2-operand fp add: order-independent
            s2  += g_ps2[other];
            cnt += g_pcnt[other];
            if (valid) {
                float lse = logf(s1);
                out[1 + row]     = lse - xl;          // ce
                out[1 + N + row] = lse - s2 / s1;     // entropy
                g_cnt[row]       = cnt;
            } else {
                out[1 + row]     = 0.0f;
                out[1 + N + row] = 0.0f;
                g_cnt[row]       = INVALID_CNT;
            }
            g_tick[row] = 0;                          // reset for next replay
            __threadfence();
            unsigned int tt = atomicAdd(&g_ticket, 1u);
            s_last = (tt == (unsigned int)(N - 1)) ? 1 : 0;
        } else {
            s_last = 0;
        }
    }
    __syncthreads();

    if (s_last) {
        // Last row-completing CTA: all rows published. Final reduction.
        __threadfence();
        float ces = 0.0f;
        int v = 0, h1 = 0, h5 = 0, h20 = 0;
        for (int i = tid; i < N; i += THREADS) {
            int c = g_cnt[i];
            ces += out[1 + i];                        // invalid rows hold 0
            if (c != INVALID_CNT) {
                v++;
                h1  += (c < 1);
                h5  += (c < 5);
                h20 += (c < 20);
            }
        }
        #pragma unroll
        for (int off = 16; off > 0; off >>= 1) {
            ces += __shfl_down_sync(0xffffffffu, ces, off);
            v   += __shfl_down_sync(0xffffffffu, v,   off);
            h1  += __shfl_down_sync(0xffffffffu, h1,  off);
            h5  += __shfl_down_sync(0xffffffffu, h5,  off);
            h20 += __shfl_down_sync(0xffffffffu, h20, off);
        }
        __shared__ float rce[NW];
        __shared__ int   rv[NW], r1[NW], r5[NW], r20[NW];
        if (lid == 0) { rce[wid] = ces; rv[wid] = v; r1[wid] = h1; r5[wid] = h5; r20[wid] = h20; }
        __syncthreads();
        if (tid == 0) {
            for (int w = 1; w < NW; w++) {
                rce[0] += rce[w]; rv[0] += rv[w];
                r1[0]  += r1[w];  r5[0] += r5[w]; r20[0] += r20[w];
            }
            float nv = (float)rv[0];
            out[0]         = rce[0] / nv;          // loss
            out[1 + 2 * N] = (float)r1[0]  / nv;   // acc@1
            out[2 + 2 * N] = (float)r5[0]  / nv;   // acc@5
            out[3 + 2 * N] = (float)r20[0] / nv;   // acc@20
            g_ticket = 0;                           // reset for next replay
        }
    }
}

extern "C" void kernel_launch(void* const* d_in, const int* in_sizes, int n_in,
                              void* d_out, int out_size) {
    const float* logits = (const float*)d_in[0];
    const int*   labels = (const int*)d_in[1];
    float*       out    = (float*)d_out;

    const int N = in_sizes[1];   // B * S = 4096 rows

    fused_kernel<<<2 * N, THREADS>>>(logits, labels, out, N);
}

// round 8
// speedup vs baseline: 1.0048x; 1.0048x over previous
#include <cuda_runtime.h>
#include <cstdint>

// Fixed shapes: logits [2, 2048, 32000] fp32, labels [2, 2048] (int32 on device)
#define VOCAB   32000
#define VVEC    (VOCAB / 4)        // 8000 float4 per row
#define SEQ     2048
#define THREADS 512                // 4 CTAs/SM -> 64/64 warps resident
#define MAIN_IT 15                 // 15 * 512 = 7680 float4
#define TAIL    (VVEC - MAIN_IT * THREADS)   // 320 float4 tail
#define NW      (THREADS / 32)     // 16 warps
#define POS_INF __int_as_float(0x7f800000)
#define INVALID_CNT 0x7fffffff

// Per-row "count of logits strictly greater than label logit".
__device__ int g_cnt[8192];
// Last-CTA ticket; self-resetting each launch (graph-replay safe).
__device__ unsigned int g_ticket = 0;

__device__ __forceinline__ void upd4(float4 v, float xl,
                                     float& s1a, float& s1b,
                                     float& s2a, float& s2b, int& cnt) {
    float ex = __expf(v.x);
    float ey = __expf(v.y);
    float ez = __expf(v.z);
    float ew = __expf(v.w);
    cnt += (v.x > xl) ? 1 : 0;
    cnt += (v.y > xl) ? 1 : 0;
    cnt += (v.z > xl) ? 1 : 0;
    cnt += (v.w > xl) ? 1 : 0;
    s1a += ex;                s1b += ey;
    s2a = fmaf(ex, v.x, s2a); s2b = fmaf(ey, v.y, s2b);
    s1a += ez;                s1b += ew;
    s2a = fmaf(ez, v.z, s2a); s2b = fmaf(ew, v.w, s2b);
}

__global__ void __launch_bounds__(THREADS, 4)   // cap regs at 32 -> 64 warps/SM
fused_kernel(const float* __restrict__ logits,
             const int* __restrict__ labels,
             float* __restrict__ out, int N) {
    const int row = blockIdx.x;
    const int s   = row % SEQ;
    const int b   = row / SEQ;
    const int tid = threadIdx.x;

    // shift labels left by one; last position of each sequence is ignored
    int lab = (s < SEQ - 1) ? labels[b * SEQ + s + 1] : -100;
    const bool valid = (lab >= 0) && (lab < VOCAB);

    const float* __restrict__ lg = logits + (long long)row * VOCAB;
    const float xl = valid ? __ldg(lg + lab) : POS_INF;

    // Direct (unshifted) accumulation: safe for |logit| << 88.
    float s1a = 0.0f, s1b = 0.0f;
    float s2a = 0.0f, s2b = 0.0f;
    int cnt = 0;

    const float4* __restrict__ lg4 = reinterpret_cast<const float4*>(lg);
    #pragma unroll 5
    for (int it = 0; it < MAIN_IT; ++it) {
        float4 v = __ldcs(&lg4[tid + it * THREADS]);   // streaming, evict-first
        upd4(v, xl, s1a, s1b, s2a, s2b, cnt);
    }
    if (tid < TAIL) {
        float4 v = __ldcs(&lg4[MAIN_IT * THREADS + tid]);
        upd4(v, xl, s1a, s1b, s2a, s2b, cnt);
    }
    float s1 = s1a + s1b;
    float s2 = s2a + s2b;

    // warp reduction (plain sums)
    #pragma unroll
    for (int off = 16; off > 0; off >>= 1) {
        s1  += __shfl_down_sync(0xffffffffu, s1, off);
        s2  += __shfl_down_sync(0xffffffffu, s2, off);
        cnt += __shfl_down_sync(0xffffffffu, cnt, off);
    }

    // cross-warp reduction (NW = 16 warps)
    __shared__ float ss1[NW], ss2[NW];
    __shared__ int   sc[NW];
    __shared__ int   s_last;
    const int wid = tid >> 5;
    const int lid = tid & 31;
    if (lid == 0) { ss1[wid] = s1; ss2[wid] = s2; sc[wid] = cnt; }
    __syncthreads();

    if (tid == 0) {
        s1 = ss1[0]; s2 = ss2[0]; cnt = sc[0];
        #pragma unroll
        for (int w = 1; w < NW; w++) { s1 += ss1[w]; s2 += ss2[w]; cnt += sc[w]; }
        if (valid) {
            float lse = logf(s1);
            out[1 + row]     = lse - xl;          // ce
            out[1 + N + row] = lse - s2 / s1;     // entropy
            g_cnt[row]       = cnt;
        } else {
            out[1 + row]     = 0.0f;
            out[1 + N + row] = 0.0f;
            g_cnt[row]       = INVALID_CNT;
        }
        // publish this row's results, then take a ticket
        __threadfence();
        unsigned int t = atomicAdd(&g_ticket, 1u);
        s_last = (t == (unsigned int)(N - 1)) ? 1 : 0;
    }
    __syncthreads();

    if (s_last) {
        // Last CTA: all rows published. Deterministic final reduction.
        __threadfence();
        float ces = 0.0f;
        int v = 0, h1 = 0, h5 = 0, h20 = 0;
        for (int i = tid; i < N; i += THREADS) {
            int c = g_cnt[i];
            ces += out[1 + i];                    // invalid rows hold 0
            if (c != INVALID_CNT) {
                v++;
                h1  += (c < 1);
                h5  += (c < 5);
                h20 += (c < 20);
            }
        }
        #pragma unroll
        for (int off = 16; off > 0; off >>= 1) {
            ces += __shfl_down_sync(0xffffffffu, ces, off);
            v   += __shfl_down_sync(0xffffffffu, v,   off);
            h1  += __shfl_down_sync(0xffffffffu, h1,  off);
            h5  += __shfl_down_sync(0xffffffffu, h5,  off);
            h20 += __shfl_down_sync(0xffffffffu, h20, off);
        }
        __shared__ float rce[NW];
        __shared__ int   rv[NW], r1[NW], r5[NW], r20[NW];
        if (lid == 0) { rce[wid] = ces; rv[wid] = v; r1[wid] = h1; r5[wid] = h5; r20[wid] = h20; }
        __syncthreads();
        if (tid == 0) {
            for (int w = 1; w < NW; w++) {
                rce[0] += rce[w]; rv[0] += rv[w];
                r1[0]  += r1[w];  r5[0] += r5[w]; r20[0] += r20[w];
            }
            float nv = (float)rv[0];
            out[0]         = rce[0] / nv;          // loss
            out[1 + 2 * N] = (float)r1[0]  / nv;   // acc@1
            out[2 + 2 * N] = (float)r5[0]  / nv;   // acc@5
            out[3 + 2 * N] = (float)r20[0] / nv;   // acc@20
            g_ticket = 0;                           // reset for next replay
        }
    }
}

extern "C" void kernel_launch(void* const* d_in, const int* in_sizes, int n_in,
                              void* d_out, int out_size) {
    const float* logits = (const float*)d_in[0];
    const int*   labels = (const int*)d_in[1];
    float*       out    = (float*)d_out;

    const int N = in_sizes[1];   // B * S = 4096 rows

    fused_kernel<<<N, THREADS>>>(logits, labels, out, N);
}

// round 9
// speedup vs baseline: 1.0621x; 1.0570x over previous
#include <cuda_runtime.h>
#include <cstdint>

// Fixed shapes: logits [2, 2048, 32000] fp32, labels [2, 2048] (int32 on device)
#define VOCAB   32000
#define VVEC    (VOCAB / 4)        // 8000 float4 per row
#define SEQ     2048
#define THREADS 320                // 8000 / 320 = 25 exact iterations, no tail
#define ITERS   (VVEC / THREADS)   // 25
#define NW      (THREADS / 32)     // 10 warps
#define POS_INF __int_as_float(0x7f800000)
#define CE_SCALE 16777216.0f       // 2^24 fixed-point scale for ce sum

// Deterministic integer accumulators (order-independent), self-resetting.
__device__ unsigned long long g_ce_fix = 0;   // sum(ce) * 2^24
__device__ unsigned long long g_stats  = 0;   // packed: v | h1<<16 | h5<<32 | h20<<48
__device__ unsigned int       g_ticket = 0;   // last-CTA ticket

__global__ void __launch_bounds__(THREADS, 6)   // cap regs at 32 -> 60 warps/SM
fused_kernel(const float* __restrict__ logits,
             const int* __restrict__ labels,
             float* __restrict__ out, int N) {
    const int row = blockIdx.x;
    const int s   = row % SEQ;
    const int b   = row / SEQ;
    const int tid = threadIdx.x;

    // shift labels left by one; last position of each sequence is ignored
    int lab = (s < SEQ - 1) ? labels[b * SEQ + s + 1] : -100;
    const bool valid = (lab >= 0) && (lab < VOCAB);

    const float* __restrict__ lg = logits + (long long)row * VOCAB;
    const float xl = valid ? __ldg(lg + lab) : POS_INF;

    // Direct (unshifted) accumulation: safe for |logit| << 88.
    // Two accumulator pairs to break FADD/FFMA dependency chains.
    float s1a = 0.0f, s1b = 0.0f;
    float s2a = 0.0f, s2b = 0.0f;
    int cnt = 0;

    const float4* __restrict__ lg4 = reinterpret_cast<const float4*>(lg);
    #pragma unroll 5
    for (int it = 0; it < ITERS; ++it) {
        float4 v = __ldcs(&lg4[tid + it * THREADS]);   // streaming, evict-first
        float ex = __expf(v.x);
        float ey = __expf(v.y);
        float ez = __expf(v.z);
        float ew = __expf(v.w);
        cnt += (v.x > xl) ? 1 : 0;
        cnt += (v.y > xl) ? 1 : 0;
        cnt += (v.z > xl) ? 1 : 0;
        cnt += (v.w > xl) ? 1 : 0;
        s1a += ex;                s1b += ey;
        s2a = fmaf(ex, v.x, s2a); s2b = fmaf(ey, v.y, s2b);
        s1a += ez;                s1b += ew;
        s2a = fmaf(ez, v.z, s2a); s2b = fmaf(ew, v.w, s2b);
    }
    float s1 = s1a + s1b;
    float s2 = s2a + s2b;

    // warp reduction (plain sums)
    #pragma unroll
    for (int off = 16; off > 0; off >>= 1) {
        s1  += __shfl_down_sync(0xffffffffu, s1, off);
        s2  += __shfl_down_sync(0xffffffffu, s2, off);
        cnt += __shfl_down_sync(0xffffffffu, cnt, off);
    }

    // cross-warp reduction (NW = 10 warps)
    __shared__ float ss1[NW], ss2[NW];
    __shared__ int   sc[NW];
    const int wid = tid >> 5;
    const int lid = tid & 31;
    if (lid == 0) { ss1[wid] = s1; ss2[wid] = s2; sc[wid] = cnt; }
    __syncthreads();

    if (tid == 0) {
        s1 = ss1[0]; s2 = ss2[0]; cnt = sc[0];
        #pragma unroll
        for (int w = 1; w < NW; w++) { s1 += ss1[w]; s2 += ss2[w]; cnt += sc[w]; }

        if (valid) {
            float lse = logf(s1);
            float ce  = lse - xl;
            out[1 + row]     = ce;                // per-token ce
            out[1 + N + row] = lse - s2 / s1;     // per-token entropy
            // Deterministic scalar accumulation (integer atomics, order-free):
            unsigned long long cef = (unsigned long long)__float2ll_rn(ce * CE_SCALE);
            unsigned long long st  = 1ull                               // n_valid
                                   | ((unsigned long long)(cnt < 1)  << 16)
                                   | ((unsigned long long)(cnt < 5)  << 32)
                                   | ((unsigned long long)(cnt < 20) << 48);
            atomicAdd(&g_ce_fix, cef);
            atomicAdd(&g_stats,  st);
        } else {
            out[1 + row]     = 0.0f;
            out[1 + N + row] = 0.0f;
        }
        __threadfence();
        unsigned int t = atomicAdd(&g_ticket, 1u);
        if (t == (unsigned int)(N - 1)) {
            // Last CTA: all rows' atomics are visible. O(1) finalize.
            __threadfence();
            unsigned long long cef = atomicAdd(&g_ce_fix, 0ull);
            unsigned long long st  = atomicAdd(&g_stats,  0ull);
            float nv  = (float)(st & 0xffffull);
            float h1  = (float)((st >> 16) & 0xffffull);
            float h5  = (float)((st >> 32) & 0xffffull);
            float h20 = (float)((st >> 48) & 0xffffull);
            float ces = (float)((double)cef / (double)CE_SCALE);
            out[0]         = ces / nv;   // loss
            out[1 + 2 * N] = h1  / nv;   // acc@1
            out[2 + 2 * N] = h5  / nv;   // acc@5
            out[3 + 2 * N] = h20 / nv;   // acc@20
            // reset for next graph replay
            g_ce_fix = 0ull;
            g_stats  = 0ull;
            g_ticket = 0u;
        }
    }
}

extern "C" void kernel_launch(void* const* d_in, const int* in_sizes, int n_in,
                              void* d_out, int out_size) {
    const float* logits = (const float*)d_in[0];
    const int*   labels = (const int*)d_in[1];
    float*       out    = (float*)d_out;

    const int N = in_sizes[1];   // B * S = 4096 rows

    fused_kernel<<<N, THREADS>>>(logits, labels, out, N);
}